// round 9
// baseline (speedup 1.0000x reference)
#include <cuda_runtime.h>
#include <cuda_fp16.h>
#include <math.h>
#include <stdint.h>

// ---------------------------------------------------------------------------
// Problem shape (fixed): B=2, S=4096, H=1024, I=3072
// ---------------------------------------------------------------------------
#define M_TOK 8192
#define H_DIM 1024
#define I_DIM 3072

// ---------------------------------------------------------------------------
// Scratch
// ---------------------------------------------------------------------------
__device__ __half g_xh [(size_t)M_TOK * H_DIM];
__device__ __half g_xl [(size_t)M_TOK * H_DIM];
__device__ __half g_wu [(size_t)I_DIM * H_DIM];
__device__ __half g_wg [(size_t)I_DIM * H_DIM];
__device__ __half g_wd [(size_t)H_DIM * I_DIM];
__device__ float g_up  [(size_t)M_TOK * I_DIM];
__device__ float g_gate[(size_t)M_TOK * I_DIM];
__device__ __half g_ph [(size_t)M_TOK * I_DIM];
__device__ __half g_pl [(size_t)M_TOK * I_DIM];
__device__ unsigned int g_amax[8];
// slots: 0=x  1=up_raw  2=gate_raw  3=t  4=p

// ---------------------------------------------------------------------------
// Helpers
// ---------------------------------------------------------------------------
__device__ __forceinline__ float qdq16(float v, float scale) {
    float q = rintf(__fdiv_rn(v, scale));
    q = fminf(fmaxf(q, -32768.0f), 32767.0f);
    return q * scale;
}
__device__ __forceinline__ float scale16(float amax) {
    return fmaxf(__fdiv_rn(amax, 32767.0f), 1e-12f);
}
__device__ __forceinline__ float silu_t(float graw, float sg) {
    float g1 = qdq16(graw, sg);
    float sig = __fdiv_rn(1.0f, 1.0f + expf(-g1));
    sig = fminf(fmaxf(rintf(sig * 65536.0f), 0.0f), 65535.0f) * (1.0f / 65536.0f);
    return g1 * sig;
}
__device__ __forceinline__ uint32_t smem_u32(const void* p) {
    uint32_t a;
    asm("{ .reg .u64 t; cvta.to.shared.u64 t, %1; cvt.u32.u64 %0, t; }"
        : "=r"(a) : "l"(p));
    return a;
}
__device__ __forceinline__ void cp16(uint32_t dst, const void* src) {
    asm volatile("cp.async.cg.shared.global [%0], [%1], 16;"
                 :: "r"(dst), "l"(src) : "memory");
}
__device__ __forceinline__ void ldsm_x4(uint32_t addr, uint32_t* r) {
    asm volatile("ldmatrix.sync.aligned.m8n8.x4.shared.b16 {%0,%1,%2,%3}, [%4];"
                 : "=r"(r[0]), "=r"(r[1]), "=r"(r[2]), "=r"(r[3]) : "r"(addr));
}
__device__ __forceinline__ void mma16816(float* c, const uint32_t* a,
                                         uint32_t b0, uint32_t b1) {
    asm volatile(
        "mma.sync.aligned.m16n8k16.row.col.f32.f16.f16.f32 "
        "{%0,%1,%2,%3}, {%4,%5,%6,%7}, {%8,%9}, {%0,%1,%2,%3};"
        : "+f"(c[0]), "+f"(c[1]), "+f"(c[2]), "+f"(c[3])
        : "r"(a[0]), "r"(a[1]), "r"(a[2]), "r"(a[3]), "r"(b0), "r"(b1));
}

// ---------------------------------------------------------------------------
// GEMM: C[M,N] = (Ah+Al)[M,K] @ Wh[N,K]^T      (fp16, fp32 accumulate)
// 128x128 tile, K-chunk 64, SW128-swizzled smem, 4-stage cp.async pipeline.
// ---------------------------------------------------------------------------
#define NSTAGES 4
#define TILE_BYTES 16384
#define STAGE_BYTES (3 * TILE_BYTES)               // Ah, Al, Wh
#define GEMM_DYN_SMEM (NSTAGES * STAGE_BYTES + 1024)

__device__ __forceinline__ void load_chunk(
    uint32_t sbase,
    const __half* __restrict__ Ah, const __half* __restrict__ Al,
    const __half* __restrict__ Bh,
    int m0, int n0, int K, int k0, int tid)
{
    #pragma unroll
    for (int u = tid; u < 1024; u += 256) {
        int r = u >> 3, cc = u & 7;
        uint32_t off = (uint32_t)(r * 128 + cc * 16);
        uint32_t sw = off ^ ((off >> 3) & 0x70);
        size_t arow = (size_t)(m0 + r) * K + k0 + cc * 8;
        size_t brow = (size_t)(n0 + r) * K + k0 + cc * 8;
        cp16(sbase + sw,                  Ah + arow);
        cp16(sbase + TILE_BYTES + sw,     Al + arow);
        cp16(sbase + 2 * TILE_BYTES + sw, Bh + brow);
    }
}

__global__ void __launch_bounds__(256, 1)
gemm_fp16_split(const __half* __restrict__ Ah, const __half* __restrict__ Al,
                const __half* __restrict__ Bh,
                float* __restrict__ C, int N, int K, unsigned int* amax_slot)
{
    extern __shared__ char dynsmem[];
    __shared__ float s_red[8];
    const int tid = threadIdx.x;
    const int wid = tid >> 5;
    const int lid = tid & 31;
    const int m0 = blockIdx.y * 128;
    const int n0 = blockIdx.x * 128;
    const int NC = K >> 6;
    uint32_t dynbase = smem_u32(dynsmem);
    dynbase = (dynbase + 1023u) & ~1023u;

    // warp grid: 4 (m) x 2 (n); warp tile 32x64
    const int m0w = (wid & 3) * 32;
    const int n0w = (wid >> 2) * 64;
    float acc[2][8][4];
    #pragma unroll
    for (int i = 0; i < 2; i++)
        #pragma unroll
        for (int j = 0; j < 8; j++)
            #pragma unroll
            for (int q = 0; q < 4; q++) acc[i][j][q] = 0.0f;

    const int g  = lid >> 3;
    const int lr = lid & 7;
    const int rsel = (g & 1) * 8 + lr;
    const int csel = (g >> 1) * 16;

    #pragma unroll
    for (int c = 0; c < NSTAGES; c++) {
        load_chunk(dynbase + c * STAGE_BYTES, Ah, Al, Bh, m0, n0, K, c * 64, tid);
        asm volatile("cp.async.commit_group;" ::: "memory");
    }

    for (int c = 0; c < NC; ++c) {
        int s = c & (NSTAGES - 1);
        asm volatile("cp.async.wait_group %0;" :: "n"(NSTAGES - 1) : "memory");
        __syncthreads();
        uint32_t sb = dynbase + s * STAGE_BYTES;
        uint32_t aH = sb, aL = sb + TILE_BYTES;
        uint32_t bH = sb + 2 * TILE_BYTES;

        #pragma unroll
        for (int ks = 0; ks < 4; ks++) {
            const int cb = ks * 32 + csel;
            uint32_t ah[2][4], al[2][4];
            #pragma unroll
            for (int mt = 0; mt < 2; mt++) {
                uint32_t off = (uint32_t)((m0w + mt * 16 + rsel) * 128 + cb);
                uint32_t sw = off ^ ((off >> 3) & 0x70);
                ldsm_x4(aH + sw, ah[mt]);
                ldsm_x4(aL + sw, al[mt]);
            }
            #pragma unroll
            for (int np = 0; np < 4; np++) {
                uint32_t off = (uint32_t)((n0w + np * 16 + rsel) * 128 + cb);
                uint32_t sw = off ^ ((off >> 3) & 0x70);
                uint32_t bh[4];
                ldsm_x4(bH + sw, bh);
                #pragma unroll
                for (int mt = 0; mt < 2; mt++) {
                    mma16816(acc[mt][np * 2 + 0], ah[mt], bh[0], bh[2]);
                    mma16816(acc[mt][np * 2 + 1], ah[mt], bh[1], bh[3]);
                    mma16816(acc[mt][np * 2 + 0], al[mt], bh[0], bh[2]);
                    mma16816(acc[mt][np * 2 + 1], al[mt], bh[1], bh[3]);
                }
            }
        }
        __syncthreads();
        if (c + NSTAGES < NC) {
            load_chunk(dynbase + s * STAGE_BYTES, Ah, Al, Bh, m0, n0, K,
                       (c + NSTAGES) * 64, tid);
        }
        asm volatile("cp.async.commit_group;" ::: "memory");
    }

    // epilogue
    const int gq = lid >> 2, q4 = lid & 3;
    float lmax = 0.0f;
    #pragma unroll
    for (int mt = 0; mt < 2; mt++) {
        #pragma unroll
        for (int nt = 0; nt < 8; nt++) {
            float* cp0 = C + (size_t)(m0 + m0w + mt * 16 + gq) * N
                           + n0 + n0w + nt * 8 + q4 * 2;
            float* cp1 = cp0 + 8 * (size_t)N;
            cp0[0] = acc[mt][nt][0]; cp0[1] = acc[mt][nt][1];
            cp1[0] = acc[mt][nt][2]; cp1[1] = acc[mt][nt][3];
            #pragma unroll
            for (int q = 0; q < 4; q++)
                lmax = fmaxf(lmax, fabsf(acc[mt][nt][q]));
        }
    }
    if (amax_slot) {
        #pragma unroll
        for (int o = 16; o; o >>= 1)
            lmax = fmaxf(lmax, __shfl_xor_sync(0xffffffffu, lmax, o));
        if (lid == 0) s_red[wid] = lmax;
        __syncthreads();
        if (tid == 0) {
            float m = s_red[0];
            #pragma unroll
            for (int i = 1; i < 8; i++) m = fmaxf(m, s_red[i]);
            atomicMax(amax_slot, __float_as_uint(m));
        }
    }
}

// ---------------------------------------------------------------------------
// Elementwise
// ---------------------------------------------------------------------------
__global__ void k_zero_amax() {
    if (threadIdx.x < 8) g_amax[threadIdx.x] = 0u;
}

__global__ void k_amax(const float4* __restrict__ p, size_t n4, int slot) {
    float m = 0.0f;
    for (size_t i = (size_t)blockIdx.x * blockDim.x + threadIdx.x; i < n4;
         i += (size_t)gridDim.x * blockDim.x) {
        float4 v = p[i];
        m = fmaxf(m, fmaxf(fmaxf(fabsf(v.x), fabsf(v.y)),
                           fmaxf(fabsf(v.z), fabsf(v.w))));
    }
    #pragma unroll
    for (int o = 16; o; o >>= 1) m = fmaxf(m, __shfl_xor_sync(0xffffffffu, m, o));
    __shared__ float red[32];
    int wid = threadIdx.x >> 5, lid = threadIdx.x & 31;
    if (lid == 0) red[wid] = m;
    __syncthreads();
    if (threadIdx.x == 0) {
        int nw = (blockDim.x + 31) >> 5;
        float mm = red[0];
        for (int i = 1; i < nw; i++) mm = fmaxf(mm, red[i]);
        atomicMax(&g_amax[slot], __float_as_uint(mm));
    }
}

// qdq16 then fp16 hi/lo split (near-exact for 16-bit grid values)
__global__ void k_quant_split(const float4* __restrict__ in,
                              __half2* __restrict__ h,
                              __half2* __restrict__ l,
                              size_t n4, int slot) {
    float s = scale16(__uint_as_float(g_amax[slot]));
    for (size_t i = (size_t)blockIdx.x * blockDim.x + threadIdx.x; i < n4;
         i += (size_t)gridDim.x * blockDim.x) {
        float4 v = in[i];
        float q[4] = {qdq16(v.x, s), qdq16(v.y, s), qdq16(v.z, s), qdq16(v.w, s)};
        __half hh[4], ll[4];
        #pragma unroll
        for (int c = 0; c < 4; c++) {
            hh[c] = __float2half_rn(q[c]);
            ll[c] = __float2half_rn(q[c] - __half2float(hh[c]));
        }
        h[2 * i]     = __halves2half2(hh[0], hh[1]);
        h[2 * i + 1] = __halves2half2(hh[2], hh[3]);
        l[2 * i]     = __halves2half2(ll[0], ll[1]);
        l[2 * i + 1] = __halves2half2(ll[2], ll[3]);
    }
}

// blockwise 4-bit weight fake qdq -> single fp16 (vectorized: 4 elems/thread)
__global__ void k_dequant_w(const float4* __restrict__ w,
                            __half2* __restrict__ oh, int n4) {
    int i = blockIdx.x * blockDim.x + threadIdx.x;
    if (i >= n4) return;
    float4 v = w[i];
    float r[4] = {v.x, v.y, v.z, v.w};
    float a = fmaxf(fmaxf(fabsf(r[0]), fabsf(r[1])),
                    fmaxf(fabsf(r[2]), fabsf(r[3])));
    #pragma unroll
    for (int o = 1; o < 8; o <<= 1)
        a = fmaxf(a, __shfl_xor_sync(0xffffffffu, a, o));
    float s = fmaxf(__fdiv_rn(a, 7.0f), 1e-12f);
    __half hh[4];
    #pragma unroll
    for (int c = 0; c < 4; c++) {
        float q = rintf(__fdiv_rn(r[c], s));
        q = fminf(fmaxf(q, -8.0f), 7.0f);
        hh[c] = __float2half_rn(q * s);
    }
    oh[2 * i]     = __halves2half2(hh[0], hh[1]);
    oh[2 * i + 1] = __halves2half2(hh[2], hh[3]);
}

// Pass 1: amax(t) from gate_raw
__global__ void k_amax_t(const float4* __restrict__ gate, size_t n4) {
    float sg = scale16(__uint_as_float(g_amax[2]));
    float m = 0.0f;
    for (size_t i = (size_t)blockIdx.x * blockDim.x + threadIdx.x; i < n4;
         i += (size_t)gridDim.x * blockDim.x) {
        float4 v = gate[i];
        m = fmaxf(m, fabsf(silu_t(v.x, sg)));
        m = fmaxf(m, fabsf(silu_t(v.y, sg)));
        m = fmaxf(m, fabsf(silu_t(v.z, sg)));
        m = fmaxf(m, fabsf(silu_t(v.w, sg)));
    }
    #pragma unroll
    for (int o = 16; o; o >>= 1) m = fmaxf(m, __shfl_xor_sync(0xffffffffu, m, o));
    __shared__ float red[32];
    int wid = threadIdx.x >> 5, lid = threadIdx.x & 31;
    if (lid == 0) red[wid] = m;
    __syncthreads();
    if (threadIdx.x == 0) {
        int nw = (blockDim.x + 31) >> 5;
        float mm = red[0];
        for (int i = 1; i < nw; i++) mm = fmaxf(mm, red[i]);
        atomicMax(&g_amax[3], __float_as_uint(mm));
    }
}

// Pass 2: amax(p) (recompute t)
__global__ void k_amax_p(const float4* __restrict__ gate,
                         const float4* __restrict__ up, size_t n4) {
    float sg = scale16(__uint_as_float(g_amax[2]));
    float st = scale16(__uint_as_float(g_amax[3]));
    float su = scale16(__uint_as_float(g_amax[1]));
    float m = 0.0f;
    for (size_t i = (size_t)blockIdx.x * blockDim.x + threadIdx.x; i < n4;
         i += (size_t)gridDim.x * blockDim.x) {
        float4 gv = gate[i];
        float4 uv = up[i];
        float rg[4] = {gv.x, gv.y, gv.z, gv.w};
        float ru[4] = {uv.x, uv.y, uv.z, uv.w};
        #pragma unroll
        for (int c = 0; c < 4; c++) {
            float g2 = qdq16(silu_t(rg[c], sg), st);
            float u  = qdq16(ru[c], su);
            m = fmaxf(m, fabsf(g2 * u));
        }
    }
    #pragma unroll
    for (int o = 16; o; o >>= 1) m = fmaxf(m, __shfl_xor_sync(0xffffffffu, m, o));
    __shared__ float red[32];
    int wid = threadIdx.x >> 5, lid = threadIdx.x & 31;
    if (lid == 0) red[wid] = m;
    __syncthreads();
    if (threadIdx.x == 0) {
        int nw = (blockDim.x + 31) >> 5;
        float mm = red[0];
        for (int i = 1; i < nw; i++) mm = fmaxf(mm, red[i]);
        atomicMax(&g_amax[4], __float_as_uint(mm));
    }
}

// Pass 3: recompute p, qdq final, split-write fp16 ph/pl
__global__ void k_write_p(const float4* __restrict__ gate,
                          const float4* __restrict__ up,
                          __half2* __restrict__ ph,
                          __half2* __restrict__ pl, size_t n4) {
    float sg = scale16(__uint_as_float(g_amax[2]));
    float st = scale16(__uint_as_float(g_amax[3]));
    float su = scale16(__uint_as_float(g_amax[1]));
    float sp = scale16(__uint_as_float(g_amax[4]));
    for (size_t i = (size_t)blockIdx.x * blockDim.x + threadIdx.x; i < n4;
         i += (size_t)gridDim.x * blockDim.x) {
        float4 gv = gate[i];
        float4 uv = up[i];
        float rg[4] = {gv.x, gv.y, gv.z, gv.w};
        float ru[4] = {uv.x, uv.y, uv.z, uv.w};
        __half hh[4], ll[4];
        #pragma unroll
        for (int c = 0; c < 4; c++) {
            float g2 = qdq16(silu_t(rg[c], sg), st);
            float u  = qdq16(ru[c], su);
            float o  = qdq16(g2 * u, sp);
            hh[c] = __float2half_rn(o);
            ll[c] = __float2half_rn(o - __half2float(hh[c]));
        }
        ph[2 * i]     = __halves2half2(hh[0], hh[1]);
        ph[2 * i + 1] = __halves2half2(hh[2], hh[3]);
        pl[2 * i]     = __halves2half2(ll[0], ll[1]);
        pl[2 * i + 1] = __halves2half2(ll[2], ll[3]);
    }
}

// ---------------------------------------------------------------------------
// Host launch
// ---------------------------------------------------------------------------
extern "C" void kernel_launch(void* const* d_in, const int* in_sizes, int n_in,
                              void* d_out, int out_size)
{
    const float* x  = (const float*)d_in[0];
    const float* wg = (const float*)d_in[1];
    const float* wu = (const float*)d_in[2];
    const float* wd = (const float*)d_in[3];
    float* out = (float*)d_out;

    __half *p_xh, *p_xl, *p_wu, *p_wg, *p_wd, *p_ph, *p_pl;
    float *p_up, *p_gate;
    unsigned int* p_amax;
    cudaGetSymbolAddress((void**)&p_xh,  g_xh);
    cudaGetSymbolAddress((void**)&p_xl,  g_xl);
    cudaGetSymbolAddress((void**)&p_wu,  g_wu);
    cudaGetSymbolAddress((void**)&p_wg,  g_wg);
    cudaGetSymbolAddress((void**)&p_wd,  g_wd);
    cudaGetSymbolAddress((void**)&p_ph,  g_ph);
    cudaGetSymbolAddress((void**)&p_pl,  g_pl);
    cudaGetSymbolAddress((void**)&p_up,  g_up);
    cudaGetSymbolAddress((void**)&p_gate, g_gate);
    cudaGetSymbolAddress((void**)&p_amax, g_amax);

    cudaFuncSetAttribute(gemm_fp16_split,
                         cudaFuncAttributeMaxDynamicSharedMemorySize, GEMM_DYN_SMEM);

    const size_t nx4 = (size_t)M_TOK * H_DIM / 4;
    const size_t ni4 = (size_t)M_TOK * I_DIM / 4;
    const int nw4 = (I_DIM * H_DIM) / 4;

    // launches 0-4
    k_zero_amax<<<1, 8>>>();                                              // 0
    k_amax<<<2048, 256>>>((const float4*)x, nx4, 0);                      // 1
    k_quant_split<<<2048, 256>>>((const float4*)x, (__half2*)p_xh,
                                 (__half2*)p_xl, nx4, 0);                 // 2
    k_dequant_w<<<nw4 / 256, 256>>>((const float4*)wu, (__half2*)p_wu, nw4); // 3
    k_dequant_w<<<nw4 / 256, 256>>>((const float4*)wg, (__half2*)p_wg, nw4); // 4

    // launch 5 (0-based): up GEMM — lands on ncu's -s 5 -c 1 capture slot
    {
        dim3 grid(I_DIM / 128, M_TOK / 128);     // (24, 64)
        gemm_fp16_split<<<grid, 256, GEMM_DYN_SMEM>>>(
            p_xh, p_xl, p_wu, p_up, I_DIM, H_DIM, p_amax + 1);            // 5
    }

    {
        dim3 grid(I_DIM / 128, M_TOK / 128);
        gemm_fp16_split<<<grid, 256, GEMM_DYN_SMEM>>>(
            p_xh, p_xl, p_wg, p_gate, I_DIM, H_DIM, p_amax + 2);          // 6
    }
    k_dequant_w<<<nw4 / 256, 256>>>((const float4*)wd, (__half2*)p_wd, nw4); // 7

    // SiLU chain (recompute; no t/p materialization)
    k_amax_t<<<4096, 256>>>((const float4*)p_gate, ni4);                  // 8
    k_amax_p<<<4096, 256>>>((const float4*)p_gate, (const float4*)p_up, ni4); // 9
    k_write_p<<<4096, 256>>>((const float4*)p_gate, (const float4*)p_up,
                             (__half2*)p_ph, (__half2*)p_pl, ni4);        // 10

    // down GEMM
    {
        dim3 grid(H_DIM / 128, M_TOK / 128);     // (8, 64)
        gemm_fp16_split<<<grid, 256, GEMM_DYN_SMEM>>>(
            p_ph, p_pl, p_wd, out, H_DIM, I_DIM, nullptr);                // 11
    }
}

// round 10
// speedup vs baseline: 1.1079x; 1.1079x over previous
#include <cuda_runtime.h>
#include <cuda_fp16.h>
#include <math.h>
#include <stdint.h>

// ---------------------------------------------------------------------------
// Problem shape (fixed): B=2, S=4096, H=1024, I=3072
// ---------------------------------------------------------------------------
#define M_TOK 8192
#define H_DIM 1024
#define I_DIM 3072

// ---------------------------------------------------------------------------
// Scratch
// ---------------------------------------------------------------------------
__device__ __half g_xh [(size_t)M_TOK * H_DIM];
__device__ __half g_xl [(size_t)M_TOK * H_DIM];
__device__ __half g_wu [(size_t)I_DIM * H_DIM];
__device__ __half g_wg [(size_t)I_DIM * H_DIM];
__device__ __half g_wd [(size_t)H_DIM * I_DIM];
__device__ float g_up  [(size_t)M_TOK * I_DIM];
__device__ float g_gate[(size_t)M_TOK * I_DIM];
__device__ __half g_ph [(size_t)M_TOK * I_DIM];
__device__ __half g_pl [(size_t)M_TOK * I_DIM];
__device__ unsigned int g_amax[8];
// slots: 0=x  1=up_raw  2=gate_raw  3=t  4=p

// ---------------------------------------------------------------------------
// Helpers
// ---------------------------------------------------------------------------
__device__ __forceinline__ float qdq16(float v, float scale) {
    float q = rintf(__fdiv_rn(v, scale));
    q = fminf(fmaxf(q, -32768.0f), 32767.0f);
    return q * scale;
}
__device__ __forceinline__ float scale16(float amax) {
    return fmaxf(__fdiv_rn(amax, 32767.0f), 1e-12f);
}
__device__ __forceinline__ float silu_t(float graw, float sg) {
    float g1 = qdq16(graw, sg);
    float sig = __fdiv_rn(1.0f, 1.0f + expf(-g1));
    sig = fminf(fmaxf(rintf(sig * 65536.0f), 0.0f), 65535.0f) * (1.0f / 65536.0f);
    return g1 * sig;
}
__device__ __forceinline__ uint32_t smem_u32(const void* p) {
    uint32_t a;
    asm("{ .reg .u64 t; cvta.to.shared.u64 t, %1; cvt.u32.u64 %0, t; }"
        : "=r"(a) : "l"(p));
    return a;
}
__device__ __forceinline__ void cp16(uint32_t dst, const void* src) {
    asm volatile("cp.async.cg.shared.global [%0], [%1], 16;"
                 :: "r"(dst), "l"(src) : "memory");
}
__device__ __forceinline__ void ldsm_x4(uint32_t addr, uint32_t* r) {
    asm volatile("ldmatrix.sync.aligned.m8n8.x4.shared.b16 {%0,%1,%2,%3}, [%4];"
                 : "=r"(r[0]), "=r"(r[1]), "=r"(r[2]), "=r"(r[3]) : "r"(addr));
}
__device__ __forceinline__ void mma16816(float* c, const uint32_t* a,
                                         uint32_t b0, uint32_t b1) {
    asm volatile(
        "mma.sync.aligned.m16n8k16.row.col.f32.f16.f16.f32 "
        "{%0,%1,%2,%3}, {%4,%5,%6,%7}, {%8,%9}, {%0,%1,%2,%3};"
        : "+f"(c[0]), "+f"(c[1]), "+f"(c[2]), "+f"(c[3])
        : "r"(a[0]), "r"(a[1]), "r"(a[2]), "r"(a[3]), "r"(b0), "r"(b1));
}

// ---------------------------------------------------------------------------
// GEMM: C[M,N] = (Ah+Al)[M,K] @ Wh[N,K]^T      (fp16, fp32 accumulate)
// 128x128 tile, K-chunk 64, SW128-swizzled smem.
// 2-stage cp.async pipeline, 96KB smem/CTA -> 2 CTAs/SM for bubble overlap.
// ---------------------------------------------------------------------------
#define NSTAGES 2
#define TILE_BYTES 16384
#define STAGE_BYTES (3 * TILE_BYTES)               // Ah, Al, Wh
#define GEMM_DYN_SMEM (NSTAGES * STAGE_BYTES + 1024)

__device__ __forceinline__ void load_chunk(
    uint32_t sbase,
    const __half* __restrict__ Ah, const __half* __restrict__ Al,
    const __half* __restrict__ Bh,
    int m0, int n0, int K, int k0, int tid)
{
    #pragma unroll
    for (int u = tid; u < 1024; u += 256) {
        int r = u >> 3, cc = u & 7;
        uint32_t off = (uint32_t)(r * 128 + cc * 16);
        uint32_t sw = off ^ ((off >> 3) & 0x70);
        size_t arow = (size_t)(m0 + r) * K + k0 + cc * 8;
        size_t brow = (size_t)(n0 + r) * K + k0 + cc * 8;
        cp16(sbase + sw,                  Ah + arow);
        cp16(sbase + TILE_BYTES + sw,     Al + arow);
        cp16(sbase + 2 * TILE_BYTES + sw, Bh + brow);
    }
}

__global__ void __launch_bounds__(256, 2)
gemm_fp16_split(const __half* __restrict__ Ah, const __half* __restrict__ Al,
                const __half* __restrict__ Bh,
                float* __restrict__ C, int N, int K, unsigned int* amax_slot)
{
    extern __shared__ char dynsmem[];
    __shared__ float s_red[8];
    const int tid = threadIdx.x;
    const int wid = tid >> 5;
    const int lid = tid & 31;
    const int m0 = blockIdx.y * 128;
    const int n0 = blockIdx.x * 128;
    const int NC = K >> 6;
    uint32_t dynbase = smem_u32(dynsmem);
    dynbase = (dynbase + 1023u) & ~1023u;

    // warp grid: 4 (m) x 2 (n); warp tile 32x64
    const int m0w = (wid & 3) * 32;
    const int n0w = (wid >> 2) * 64;
    float acc[2][8][4];
    #pragma unroll
    for (int i = 0; i < 2; i++)
        #pragma unroll
        for (int j = 0; j < 8; j++)
            #pragma unroll
            for (int q = 0; q < 4; q++) acc[i][j][q] = 0.0f;

    const int g  = lid >> 3;
    const int lr = lid & 7;
    const int rsel = (g & 1) * 8 + lr;
    const int csel = (g >> 1) * 16;

    #pragma unroll
    for (int c = 0; c < NSTAGES; c++) {
        load_chunk(dynbase + c * STAGE_BYTES, Ah, Al, Bh, m0, n0, K, c * 64, tid);
        asm volatile("cp.async.commit_group;" ::: "memory");
    }

    for (int c = 0; c < NC; ++c) {
        int s = c & (NSTAGES - 1);
        asm volatile("cp.async.wait_group %0;" :: "n"(NSTAGES - 1) : "memory");
        __syncthreads();
        uint32_t sb = dynbase + s * STAGE_BYTES;
        uint32_t aH = sb, aL = sb + TILE_BYTES;
        uint32_t bH = sb + 2 * TILE_BYTES;

        #pragma unroll
        for (int ks = 0; ks < 4; ks++) {
            const int cb = ks * 32 + csel;
            uint32_t ah[2][4], al[2][4];
            #pragma unroll
            for (int mt = 0; mt < 2; mt++) {
                uint32_t off = (uint32_t)((m0w + mt * 16 + rsel) * 128 + cb);
                uint32_t sw = off ^ ((off >> 3) & 0x70);
                ldsm_x4(aH + sw, ah[mt]);
                ldsm_x4(aL + sw, al[mt]);
            }
            #pragma unroll
            for (int np = 0; np < 4; np++) {
                uint32_t off = (uint32_t)((n0w + np * 16 + rsel) * 128 + cb);
                uint32_t sw = off ^ ((off >> 3) & 0x70);
                uint32_t bh[4];
                ldsm_x4(bH + sw, bh);
                #pragma unroll
                for (int mt = 0; mt < 2; mt++) {
                    mma16816(acc[mt][np * 2 + 0], ah[mt], bh[0], bh[2]);
                    mma16816(acc[mt][np * 2 + 1], ah[mt], bh[1], bh[3]);
                    mma16816(acc[mt][np * 2 + 0], al[mt], bh[0], bh[2]);
                    mma16816(acc[mt][np * 2 + 1], al[mt], bh[1], bh[3]);
                }
            }
        }
        __syncthreads();
        if (c + NSTAGES < NC) {
            load_chunk(dynbase + s * STAGE_BYTES, Ah, Al, Bh, m0, n0, K,
                       (c + NSTAGES) * 64, tid);
        }
        asm volatile("cp.async.commit_group;" ::: "memory");
    }

    // epilogue
    const int gq = lid >> 2, q4 = lid & 3;
    float lmax = 0.0f;
    #pragma unroll
    for (int mt = 0; mt < 2; mt++) {
        #pragma unroll
        for (int nt = 0; nt < 8; nt++) {
            float* cp0 = C + (size_t)(m0 + m0w + mt * 16 + gq) * N
                           + n0 + n0w + nt * 8 + q4 * 2;
            float* cp1 = cp0 + 8 * (size_t)N;
            cp0[0] = acc[mt][nt][0]; cp0[1] = acc[mt][nt][1];
            cp1[0] = acc[mt][nt][2]; cp1[1] = acc[mt][nt][3];
            #pragma unroll
            for (int q = 0; q < 4; q++)
                lmax = fmaxf(lmax, fabsf(acc[mt][nt][q]));
        }
    }
    if (amax_slot) {
        #pragma unroll
        for (int o = 16; o; o >>= 1)
            lmax = fmaxf(lmax, __shfl_xor_sync(0xffffffffu, lmax, o));
        if (lid == 0) s_red[wid] = lmax;
        __syncthreads();
        if (tid == 0) {
            float m = s_red[0];
            #pragma unroll
            for (int i = 1; i < 8; i++) m = fmaxf(m, s_red[i]);
            atomicMax(amax_slot, __float_as_uint(m));
        }
    }
}

// ---------------------------------------------------------------------------
// Elementwise
// ---------------------------------------------------------------------------
__global__ void k_zero_amax() {
    if (threadIdx.x < 8) g_amax[threadIdx.x] = 0u;
}

__global__ void k_amax(const float4* __restrict__ p, size_t n4, int slot) {
    float m = 0.0f;
    for (size_t i = (size_t)blockIdx.x * blockDim.x + threadIdx.x; i < n4;
         i += (size_t)gridDim.x * blockDim.x) {
        float4 v = p[i];
        m = fmaxf(m, fmaxf(fmaxf(fabsf(v.x), fabsf(v.y)),
                           fmaxf(fabsf(v.z), fabsf(v.w))));
    }
    #pragma unroll
    for (int o = 16; o; o >>= 1) m = fmaxf(m, __shfl_xor_sync(0xffffffffu, m, o));
    __shared__ float red[32];
    int wid = threadIdx.x >> 5, lid = threadIdx.x & 31;
    if (lid == 0) red[wid] = m;
    __syncthreads();
    if (threadIdx.x == 0) {
        int nw = (blockDim.x + 31) >> 5;
        float mm = red[0];
        for (int i = 1; i < nw; i++) mm = fmaxf(mm, red[i]);
        atomicMax(&g_amax[slot], __float_as_uint(mm));
    }
}

// qdq16 then fp16 hi/lo split (near-exact for 16-bit grid values)
__global__ void k_quant_split(const float4* __restrict__ in,
                              __half2* __restrict__ h,
                              __half2* __restrict__ l,
                              size_t n4, int slot) {
    float s = scale16(__uint_as_float(g_amax[slot]));
    for (size_t i = (size_t)blockIdx.x * blockDim.x + threadIdx.x; i < n4;
         i += (size_t)gridDim.x * blockDim.x) {
        float4 v = in[i];
        float q[4] = {qdq16(v.x, s), qdq16(v.y, s), qdq16(v.z, s), qdq16(v.w, s)};
        __half hh[4], ll[4];
        #pragma unroll
        for (int c = 0; c < 4; c++) {
            hh[c] = __float2half_rn(q[c]);
            ll[c] = __float2half_rn(q[c] - __half2float(hh[c]));
        }
        h[2 * i]     = __halves2half2(hh[0], hh[1]);
        h[2 * i + 1] = __halves2half2(hh[2], hh[3]);
        l[2 * i]     = __halves2half2(ll[0], ll[1]);
        l[2 * i + 1] = __halves2half2(ll[2], ll[3]);
    }
}

// blockwise 4-bit weight fake qdq -> single fp16 (vectorized: 4 elems/thread)
__global__ void k_dequant_w(const float4* __restrict__ w,
                            __half2* __restrict__ oh, int n4) {
    int i = blockIdx.x * blockDim.x + threadIdx.x;
    if (i >= n4) return;
    float4 v = w[i];
    float r[4] = {v.x, v.y, v.z, v.w};
    float a = fmaxf(fmaxf(fabsf(r[0]), fabsf(r[1])),
                    fmaxf(fabsf(r[2]), fabsf(r[3])));
    #pragma unroll
    for (int o = 1; o < 8; o <<= 1)
        a = fmaxf(a, __shfl_xor_sync(0xffffffffu, a, o));
    float s = fmaxf(__fdiv_rn(a, 7.0f), 1e-12f);
    __half hh[4];
    #pragma unroll
    for (int c = 0; c < 4; c++) {
        float q = rintf(__fdiv_rn(r[c], s));
        q = fminf(fmaxf(q, -8.0f), 7.0f);
        hh[c] = __float2half_rn(q * s);
    }
    oh[2 * i]     = __halves2half2(hh[0], hh[1]);
    oh[2 * i + 1] = __halves2half2(hh[2], hh[3]);
}

// Pass 1: amax(t) from gate_raw
__global__ void k_amax_t(const float4* __restrict__ gate, size_t n4) {
    float sg = scale16(__uint_as_float(g_amax[2]));
    float m = 0.0f;
    for (size_t i = (size_t)blockIdx.x * blockDim.x + threadIdx.x; i < n4;
         i += (size_t)gridDim.x * blockDim.x) {
        float4 v = gate[i];
        m = fmaxf(m, fabsf(silu_t(v.x, sg)));
        m = fmaxf(m, fabsf(silu_t(v.y, sg)));
        m = fmaxf(m, fabsf(silu_t(v.z, sg)));
        m = fmaxf(m, fabsf(silu_t(v.w, sg)));
    }
    #pragma unroll
    for (int o = 16; o; o >>= 1) m = fmaxf(m, __shfl_xor_sync(0xffffffffu, m, o));
    __shared__ float red[32];
    int wid = threadIdx.x >> 5, lid = threadIdx.x & 31;
    if (lid == 0) red[wid] = m;
    __syncthreads();
    if (threadIdx.x == 0) {
        int nw = (blockDim.x + 31) >> 5;
        float mm = red[0];
        for (int i = 1; i < nw; i++) mm = fmaxf(mm, red[i]);
        atomicMax(&g_amax[3], __float_as_uint(mm));
    }
}

// Pass 2: amax(p) (recompute t)
__global__ void k_amax_p(const float4* __restrict__ gate,
                         const float4* __restrict__ up, size_t n4) {
    float sg = scale16(__uint_as_float(g_amax[2]));
    float st = scale16(__uint_as_float(g_amax[3]));
    float su = scale16(__uint_as_float(g_amax[1]));
    float m = 0.0f;
    for (size_t i = (size_t)blockIdx.x * blockDim.x + threadIdx.x; i < n4;
         i += (size_t)gridDim.x * blockDim.x) {
        float4 gv = gate[i];
        float4 uv = up[i];
        float rg[4] = {gv.x, gv.y, gv.z, gv.w};
        float ru[4] = {uv.x, uv.y, uv.z, uv.w};
        #pragma unroll
        for (int c = 0; c < 4; c++) {
            float g2 = qdq16(silu_t(rg[c], sg), st);
            float u  = qdq16(ru[c], su);
            m = fmaxf(m, fabsf(g2 * u));
        }
    }
    #pragma unroll
    for (int o = 16; o; o >>= 1) m = fmaxf(m, __shfl_xor_sync(0xffffffffu, m, o));
    __shared__ float red[32];
    int wid = threadIdx.x >> 5, lid = threadIdx.x & 31;
    if (lid == 0) red[wid] = m;
    __syncthreads();
    if (threadIdx.x == 0) {
        int nw = (blockDim.x + 31) >> 5;
        float mm = red[0];
        for (int i = 1; i < nw; i++) mm = fmaxf(mm, red[i]);
        atomicMax(&g_amax[4], __float_as_uint(mm));
    }
}

// Pass 3: recompute p, qdq final, split-write fp16 ph/pl
__global__ void k_write_p(const float4* __restrict__ gate,
                          const float4* __restrict__ up,
                          __half2* __restrict__ ph,
                          __half2* __restrict__ pl, size_t n4) {
    float sg = scale16(__uint_as_float(g_amax[2]));
    float st = scale16(__uint_as_float(g_amax[3]));
    float su = scale16(__uint_as_float(g_amax[1]));
    float sp = scale16(__uint_as_float(g_amax[4]));
    for (size_t i = (size_t)blockIdx.x * blockDim.x + threadIdx.x; i < n4;
         i += (size_t)gridDim.x * blockDim.x) {
        float4 gv = gate[i];
        float4 uv = up[i];
        float rg[4] = {gv.x, gv.y, gv.z, gv.w};
        float ru[4] = {uv.x, uv.y, uv.z, uv.w};
        __half hh[4], ll[4];
        #pragma unroll
        for (int c = 0; c < 4; c++) {
            float g2 = qdq16(silu_t(rg[c], sg), st);
            float u  = qdq16(ru[c], su);
            float o  = qdq16(g2 * u, sp);
            hh[c] = __float2half_rn(o);
            ll[c] = __float2half_rn(o - __half2float(hh[c]));
        }
        ph[2 * i]     = __halves2half2(hh[0], hh[1]);
        ph[2 * i + 1] = __halves2half2(hh[2], hh[3]);
        pl[2 * i]     = __halves2half2(ll[0], ll[1]);
        pl[2 * i + 1] = __halves2half2(ll[2], ll[3]);
    }
}

// ---------------------------------------------------------------------------
// Host launch
// ---------------------------------------------------------------------------
extern "C" void kernel_launch(void* const* d_in, const int* in_sizes, int n_in,
                              void* d_out, int out_size)
{
    const float* x  = (const float*)d_in[0];
    const float* wg = (const float*)d_in[1];
    const float* wu = (const float*)d_in[2];
    const float* wd = (const float*)d_in[3];
    float* out = (float*)d_out;

    __half *p_xh, *p_xl, *p_wu, *p_wg, *p_wd, *p_ph, *p_pl;
    float *p_up, *p_gate;
    unsigned int* p_amax;
    cudaGetSymbolAddress((void**)&p_xh,  g_xh);
    cudaGetSymbolAddress((void**)&p_xl,  g_xl);
    cudaGetSymbolAddress((void**)&p_wu,  g_wu);
    cudaGetSymbolAddress((void**)&p_wg,  g_wg);
    cudaGetSymbolAddress((void**)&p_wd,  g_wd);
    cudaGetSymbolAddress((void**)&p_ph,  g_ph);
    cudaGetSymbolAddress((void**)&p_pl,  g_pl);
    cudaGetSymbolAddress((void**)&p_up,  g_up);
    cudaGetSymbolAddress((void**)&p_gate, g_gate);
    cudaGetSymbolAddress((void**)&p_amax, g_amax);

    cudaFuncSetAttribute(gemm_fp16_split,
                         cudaFuncAttributeMaxDynamicSharedMemorySize, GEMM_DYN_SMEM);

    const size_t nx4 = (size_t)M_TOK * H_DIM / 4;
    const size_t ni4 = (size_t)M_TOK * I_DIM / 4;
    const int nw4 = (I_DIM * H_DIM) / 4;

    k_zero_amax<<<1, 8>>>();
    k_amax<<<2048, 256>>>((const float4*)x, nx4, 0);
    k_quant_split<<<2048, 256>>>((const float4*)x, (__half2*)p_xh,
                                 (__half2*)p_xl, nx4, 0);
    k_dequant_w<<<nw4 / 256, 256>>>((const float4*)wu, (__half2*)p_wu, nw4);
    k_dequant_w<<<nw4 / 256, 256>>>((const float4*)wg, (__half2*)p_wg, nw4);

    // up GEMM
    {
        dim3 grid(I_DIM / 128, M_TOK / 128);     // (24, 64)
        gemm_fp16_split<<<grid, 256, GEMM_DYN_SMEM>>>(
            p_xh, p_xl, p_wu, p_up, I_DIM, H_DIM, p_amax + 1);
    }
    // gate GEMM
    {
        dim3 grid(I_DIM / 128, M_TOK / 128);
        gemm_fp16_split<<<grid, 256, GEMM_DYN_SMEM>>>(
            p_xh, p_xl, p_wg, p_gate, I_DIM, H_DIM, p_amax + 2);
    }
    k_dequant_w<<<nw4 / 256, 256>>>((const float4*)wd, (__half2*)p_wd, nw4);

    // SiLU chain (recompute; no t/p materialization)
    k_amax_t<<<4096, 256>>>((const float4*)p_gate, ni4);
    k_amax_p<<<4096, 256>>>((const float4*)p_gate, (const float4*)p_up, ni4);
    k_write_p<<<4096, 256>>>((const float4*)p_gate, (const float4*)p_up,
                             (__half2*)p_ph, (__half2*)p_pl, ni4);

    // down GEMM
    {
        dim3 grid(H_DIM / 128, M_TOK / 128);     // (8, 64)
        gemm_fp16_split<<<grid, 256, GEMM_DYN_SMEM>>>(
            p_ph, p_pl, p_wd, out, H_DIM, I_DIM, nullptr);
    }
}